// round 6
// baseline (speedup 1.0000x reference)
#include <cuda_runtime.h>
#include <cstdint>

#define N_NODES 8192
#define FIN 256
#define FOUT 64
#define GAT_ALPHA 0.2f
#define EXP_M10 4.539992976e-5f   // expf(-10)
#define LOG2E 1.4426950408889634f

// ---- k_mma geometry ----
#define TM 128                       // i rows per CTA
#define TKJ 64                       // j per tile
#define JSPLIT 4
#define KCHUNK (N_NODES / JSPLIT)    // 2048
#define NT (KCHUNK / TKJ)            // 32 tiles

// ---- scratch (allocation-free rule) ----
__device__ float g_s1[N_NODES];
__device__ float g_s2[N_NODES];
__device__ float g_hf32[(size_t)N_NODES * FOUT];   // tf32-rounded h, 2 MB
__device__ float g_part[JSPLIT][N_NODES][FOUT];    // 8 MB
__device__ float g_lpart[JSPLIT][N_NODES];         // 128 KB

__device__ __forceinline__ float tf32r(float x) {
    uint32_t r;
    asm("cvt.rna.tf32.f32 %0, %1;" : "=r"(r) : "f"(x));
    return __uint_as_float(r);
}

__device__ __forceinline__ float ex2(float x) {
    float r;
    asm("ex2.approx.f32 %0, %1;" : "=f"(r) : "f"(x));
    return r;
}

__device__ __forceinline__ void mma_tf32(float c[4],
    uint32_t a0, uint32_t a1, uint32_t a2, uint32_t a3,
    uint32_t b0, uint32_t b1)
{
    asm volatile(
        "mma.sync.aligned.m16n8k8.row.col.f32.tf32.tf32.f32 "
        "{%0,%1,%2,%3}, {%4,%5,%6,%7}, {%8,%9}, {%0,%1,%2,%3};"
        : "+f"(c[0]), "+f"(c[1]), "+f"(c[2]), "+f"(c[3])
        : "r"(a0), "r"(a1), "r"(a2), "r"(a3), "r"(b0), "r"(b1));
}

// ============================================================================
// Kernel 1: h = input @ W (smem-tiled fp32); emit s1, s2 (exact) + tf32 h.
// Grid: 256 blocks x 32 rows, 256 threads.
// ============================================================================
__global__ __launch_bounds__(256) void k_h(
    const float* __restrict__ input,   // [N, FIN]
    const float* __restrict__ W,       // [FIN, FOUT]
    const float* __restrict__ a)       // [2*FOUT]
{
    __shared__ float pool[6144];       // in_s[32][64] @0 | w_s[64][64] @2048
    const int t = threadIdx.x;
    const int i0 = blockIdx.x * 32;
    const int f4 = (t & 15) * 4;
    const int i2 = (t >> 4) * 2;

    float c[2][4];
    #pragma unroll
    for (int r = 0; r < 2; ++r) { c[r][0]=0.f; c[r][1]=0.f; c[r][2]=0.f; c[r][3]=0.f; }

    const float4* in4 = reinterpret_cast<const float4*>(input);
    const float4* W4  = reinterpret_cast<const float4*>(W);

    for (int kc = 0; kc < 4; ++kc) {
        __syncthreads();
        #pragma unroll
        for (int r = 0; r < 2; ++r) {
            const int idx = t + r * 256;
            const int row = idx >> 4, c4 = idx & 15;
            *reinterpret_cast<float4*>(&pool[row * 64 + c4 * 4]) =
                in4[(size_t)(i0 + row) * 64 + kc * 16 + c4];
        }
        #pragma unroll
        for (int r = 0; r < 4; ++r) {
            const int idx = t + r * 256;
            const int row = idx >> 4, c4 = idx & 15;
            *reinterpret_cast<float4*>(&pool[2048 + row * 64 + c4 * 4]) =
                W4[(size_t)(kc * 64 + row) * 16 + c4];
        }
        __syncthreads();
        #pragma unroll 8
        for (int kk = 0; kk < 64; ++kk) {
            const float4 wv = *reinterpret_cast<const float4*>(&pool[2048 + kk * 64 + f4]);
            #pragma unroll
            for (int r = 0; r < 2; ++r) {
                const float iv = pool[(i2 + r) * 64 + kk];
                c[r][0] = fmaf(iv, wv.x, c[r][0]);
                c[r][1] = fmaf(iv, wv.y, c[r][1]);
                c[r][2] = fmaf(iv, wv.z, c[r][2]);
                c[r][3] = fmaf(iv, wv.w, c[r][3]);
            }
        }
    }

    // g_hf32 (tf32-rounded)
    #pragma unroll
    for (int r = 0; r < 2; ++r) {
        float4 v;
        v.x = tf32r(c[r][0]); v.y = tf32r(c[r][1]);
        v.z = tf32r(c[r][2]); v.w = tf32r(c[r][3]);
        *reinterpret_cast<float4*>(g_hf32 + (size_t)(i0 + i2 + r) * FOUT + f4) = v;
    }

    // stage fp32 h into padded smem for exact s1/s2
    __syncthreads();
    #pragma unroll
    for (int r = 0; r < 2; ++r) {
        float* row = &pool[(i2 + r) * 65 + f4];
        row[0] = c[r][0]; row[1] = c[r][1]; row[2] = c[r][2]; row[3] = c[r][3];
    }
    __syncthreads();

    if (t < 32) {
        float s1 = 0.f, s2 = 0.f;
        #pragma unroll 8
        for (int f = 0; f < 64; ++f) {
            const float hv = pool[t * 65 + f];
            s1 = fmaf(hv, __ldg(&a[f]), s1);
            s2 = fmaf(hv, __ldg(&a[64 + f]), s2);
        }
        g_s1[i0 + t] = s1;
        g_s2[i0 + t] = s2;
    }
}

// ============================================================================
// Kernel 2: tf32 HMMA GEMM, A fragments built IN REGISTERS, B fragment-packed.
// Grid: (64 i-tiles, 4 j-splits), 256 threads = 8 warps.
// ============================================================================
__global__ __launch_bounds__(256, 2) void k_mma(const int* __restrict__ adj)
{
    __shared__ float s2s[KCHUNK];                    // 8 KB (prescaled by LOG2E)
    __shared__ __align__(16) float Bf[16 * 384];     // 24 KB fragment-packed B

    const int t = threadIdx.x;
    const int w = t >> 5;
    const int l = t & 31;
    const int gid = l >> 2;
    const int tig = l & 3;
    const int i0 = blockIdx.x * TM;
    const int js = blockIdx.y;
    const int j0 = js * KCHUNK;

    const int r0 = w * 16 + gid;      // fragment rows owned by this lane
    const int r1 = r0 + 8;

    // stage prescaled s2 chunk
    for (int k = t; k < KCHUNK; k += 256)
        s2s[k] = g_s2[j0 + k] * LOG2E;

    const float s1p0 = g_s1[i0 + r0] * LOG2E;
    const float s1p1 = g_s1[i0 + r1] * LOG2E;

    const int* ar0 = adj + (size_t)(i0 + r0) * N_NODES + j0 + tig;
    const int* ar1 = adj + (size_t)(i0 + r1) * N_NODES + j0 + tig;

    float c[8][4];
    #pragma unroll
    for (int nt = 0; nt < 8; ++nt) {
        c[nt][0] = 0.f; c[nt][1] = 0.f; c[nt][2] = 0.f; c[nt][3] = 0.f;
    }
    float l0 = 0.f, l1 = 0.f;

    // B staging mapping
    const int jr   = t >> 2;          // 0..63 local j row
    const int q0   = t & 3;
    const int blk  = jr >> 2;         // ks*2+half  = jr>>2
    const int tigw = jr & 3;

    __syncthreads();

    for (int tile = 0; tile < NT; ++tile) {
        const int jt = tile * TKJ;    // local j offset

        // --- adj loads for this tile (32 scalars, issued up front) ---
        int av[8][4];
        #pragma unroll
        for (int ks = 0; ks < 8; ++ks) {
            av[ks][0] = __ldg(ar0 + jt + ks * 8);
            av[ks][1] = __ldg(ar1 + jt + ks * 8);
            av[ks][2] = __ldg(ar0 + jt + ks * 8 + 4);
            av[ks][3] = __ldg(ar1 + jt + ks * 8 + 4);
        }

        // --- stage B fragments: Bf[blk][lane*12 + nt] = h[j][f] ---
        #pragma unroll
        for (int m = 0; m < 4; ++m) {
            const int q = q0 + 4 * m;
            const float4 hv = *reinterpret_cast<const float4*>(
                g_hf32 + (size_t)(j0 + jt + jr) * FOUT + 4 * q);
            const int nt = q >> 1;
            const int gb = 4 * (q & 1);
            float* dst = Bf + blk * 384 + tigw * 12 + nt;
            dst[(gb + 0) * 48] = hv.x;
            dst[(gb + 1) * 48] = hv.y;
            dst[(gb + 2) * 48] = hv.z;
            dst[(gb + 3) * 48] = hv.w;
        }
        __syncthreads();

        // --- per k-step: build 4 A regs, load B frags (4x LDS.128), 8 MMAs ---
        #pragma unroll
        for (int ks = 0; ks < 8; ++ks) {
            const float s2a = s2s[jt + ks * 8 + tig];
            const float s2b = s2s[jt + ks * 8 + tig + 4];
            float x, wv;
            uint32_t a0, a1, a2, a3;
            x = s1p0 + s2a; wv = (av[ks][0] > 0) ? ex2(fmaxf(x, 0.2f * x)) : EXP_M10;
            asm("cvt.rna.tf32.f32 %0, %1;" : "=r"(a0) : "f"(wv));
            x = s1p1 + s2a; wv = (av[ks][1] > 0) ? ex2(fmaxf(x, 0.2f * x)) : EXP_M10;
            asm("cvt.rna.tf32.f32 %0, %1;" : "=r"(a1) : "f"(wv));
            x = s1p0 + s2b; wv = (av[ks][2] > 0) ? ex2(fmaxf(x, 0.2f * x)) : EXP_M10;
            asm("cvt.rna.tf32.f32 %0, %1;" : "=r"(a2) : "f"(wv));
            x = s1p1 + s2b; wv = (av[ks][3] > 0) ? ex2(fmaxf(x, 0.2f * x)) : EXP_M10;
            asm("cvt.rna.tf32.f32 %0, %1;" : "=r"(a3) : "f"(wv));

            l0 += __uint_as_float(a0) + __uint_as_float(a2);
            l1 += __uint_as_float(a1) + __uint_as_float(a3);

            const float4* b0p = reinterpret_cast<const float4*>(Bf + (2 * ks) * 384 + l * 12);
            const float4* b1p = reinterpret_cast<const float4*>(Bf + (2 * ks + 1) * 384 + l * 12);
            const float4 b0lo = b0p[0], b0hi = b0p[1];
            const float4 b1lo = b1p[0], b1hi = b1p[1];
            const float b0a[8] = {b0lo.x, b0lo.y, b0lo.z, b0lo.w,
                                  b0hi.x, b0hi.y, b0hi.z, b0hi.w};
            const float b1a[8] = {b1lo.x, b1lo.y, b1lo.z, b1lo.w,
                                  b1hi.x, b1hi.y, b1hi.z, b1hi.w};
            #pragma unroll
            for (int nt = 0; nt < 8; ++nt)
                mma_tf32(c[nt], a0, a1, a2, a3,
                         __float_as_uint(b0a[nt]), __float_as_uint(b1a[nt]));
        }
        __syncthreads();
    }

    // --- epilogue: write D partials ---
    #pragma unroll
    for (int nt = 0; nt < 8; ++nt) {
        const int col = nt * 8 + tig * 2;
        float* p0 = &g_part[js][i0 + r0][col];
        float* p1 = &g_part[js][i0 + r1][col];
        *reinterpret_cast<float2*>(p0) = make_float2(c[nt][0], c[nt][1]);
        *reinterpret_cast<float2*>(p1) = make_float2(c[nt][2], c[nt][3]);
    }

    // --- l partials: reduce across the 4 lanes (tig group) sharing each row ---
    l0 += __shfl_xor_sync(0xffffffffu, l0, 1);
    l0 += __shfl_xor_sync(0xffffffffu, l0, 2);
    l1 += __shfl_xor_sync(0xffffffffu, l1, 1);
    l1 += __shfl_xor_sync(0xffffffffu, l1, 2);
    if (tig == 0) {
        g_lpart[js][i0 + r0] = l0;
        g_lpart[js][i0 + r1] = l1;
    }
}

// ============================================================================
// Kernel 3: reduce 4 partials, normalize, ELU
// ============================================================================
__global__ __launch_bounds__(256) void k_reduce(float* __restrict__ out)
{
    const int idx = blockIdx.x * 256 + threadIdx.x;   // over N*FOUT
    const int i = idx >> 6;
    const int f = idx & 63;

    float s = 0.0f, lsum = 0.0f;
    #pragma unroll
    for (int p = 0; p < JSPLIT; ++p) {
        s    += g_part[p][i][f];
        lsum += g_lpart[p][i];
    }
    const float v = s / lsum;
    out[idx] = (v > 0.0f) ? v : (__expf(v) - 1.0f);
}

// ============================================================================
extern "C" void kernel_launch(void* const* d_in, const int* in_sizes, int n_in,
                              void* d_out, int out_size)
{
    const float* input = (const float*)d_in[0];  // [8192, 256]
    const int*   adj   = (const int*)  d_in[1];  // [8192, 8192]
    const float* W     = (const float*)d_in[2];  // [256, 64]
    const float* a     = (const float*)d_in[3];  // [128, 1]
    float* out = (float*)d_out;                  // [8192, 64]

    k_h<<<N_NODES / 32, 256>>>(input, W, a);
    k_mma<<<dim3(N_NODES / TM, JSPLIT), 256>>>(adj);
    k_reduce<<<(N_NODES * FOUT) / 256, 256>>>(out);
}

// round 7
// speedup vs baseline: 1.0987x; 1.0987x over previous
#include <cuda_runtime.h>
#include <cstdint>

#define N_NODES 8192
#define FIN 256
#define FOUT 64
#define EXP_M10 4.539992976e-5f   // expf(-10)
#define LOG2E 1.4426950408889634f

// ---- k_mma geometry ----
#define TM 128                       // i rows per CTA unit
#define TKJ 64                       // j per tile
#define JSPLIT 8
#define KCHUNK (N_NODES / JSPLIT)    // 1024
#define NT (KCHUNK / TKJ)            // 16 tiles per unit
#define NUNITS (64 * JSPLIT)         // 512
#define GRID_MMA 296                 // 2 per SM, persistent

// padded smem strides (bank-conflict-free fragment LDS)
#define A_STRIDE 68                  // 68 mod 32 = 4 : gid*4+tig distinct
#define B_STRIDE 72                  // 72 mod 32 = 8 : tig*8+gid distinct
#define SM_B_OFF (TM * A_STRIDE)                 // 8704
#define SM_S2_OFF (SM_B_OFF + TKJ * B_STRIDE)    // 8704+4608=13312
#define SMEM_FLOATS (SM_S2_OFF + KCHUNK)         // 14336
#define SMEM_BYTES (SMEM_FLOATS * 4)             // 57344

// ---- scratch (allocation-free rule) ----
__device__ float g_s1[N_NODES];                    // prescaled by LOG2E
__device__ float g_s2[N_NODES];                    // prescaled by LOG2E
__device__ float g_hf32[(size_t)N_NODES * FOUT];   // tf32-rounded h, 2 MB
__device__ float g_part[JSPLIT][N_NODES][FOUT];    // 16 MB
__device__ float g_lpart[JSPLIT][N_NODES];         // 256 KB
__device__ int   g_ctr;

__device__ __forceinline__ float tf32r(float x) {
    uint32_t r;
    asm("cvt.rna.tf32.f32 %0, %1;" : "=r"(r) : "f"(x));
    return __uint_as_float(r);
}

__device__ __forceinline__ float ex2(float x) {
    float r;
    asm("ex2.approx.f32 %0, %1;" : "=f"(r) : "f"(x));
    return r;
}

__device__ __forceinline__ void mma_tf32(float c[4],
    uint32_t a0, uint32_t a1, uint32_t a2, uint32_t a3,
    uint32_t b0, uint32_t b1)
{
    asm volatile(
        "mma.sync.aligned.m16n8k8.row.col.f32.tf32.tf32.f32 "
        "{%0,%1,%2,%3}, {%4,%5,%6,%7}, {%8,%9}, {%0,%1,%2,%3};"
        : "+f"(c[0]), "+f"(c[1]), "+f"(c[2]), "+f"(c[3])
        : "r"(a0), "r"(a1), "r"(a2), "r"(a3), "r"(b0), "r"(b1));
}

// ============================================================================
// Kernel 1: h = input @ W; emit prescaled s1,s2 + tf32 h; reset work counter.
// ============================================================================
__global__ __launch_bounds__(256) void k_h(
    const float* __restrict__ input,   // [N, FIN]
    const float* __restrict__ W,       // [FIN, FOUT]
    const float* __restrict__ a)       // [2*FOUT]
{
    __shared__ float pool[6144];       // in_s[32][64] @0 | w_s[64][64] @2048
    const int t = threadIdx.x;
    const int i0 = blockIdx.x * 32;
    const int f4 = (t & 15) * 4;
    const int i2 = (t >> 4) * 2;

    if (blockIdx.x == 0 && t == 0) g_ctr = 0;

    float c[2][4];
    #pragma unroll
    for (int r = 0; r < 2; ++r) { c[r][0]=0.f; c[r][1]=0.f; c[r][2]=0.f; c[r][3]=0.f; }

    const float4* in4 = reinterpret_cast<const float4*>(input);
    const float4* W4  = reinterpret_cast<const float4*>(W);

    for (int kc = 0; kc < 4; ++kc) {
        __syncthreads();
        #pragma unroll
        for (int r = 0; r < 2; ++r) {
            const int idx = t + r * 256;
            const int row = idx >> 4, c4 = idx & 15;
            *reinterpret_cast<float4*>(&pool[row * 64 + c4 * 4]) =
                in4[(size_t)(i0 + row) * 64 + kc * 16 + c4];
        }
        #pragma unroll
        for (int r = 0; r < 4; ++r) {
            const int idx = t + r * 256;
            const int row = idx >> 4, c4 = idx & 15;
            *reinterpret_cast<float4*>(&pool[2048 + row * 64 + c4 * 4]) =
                W4[(size_t)(kc * 64 + row) * 16 + c4];
        }
        __syncthreads();
        #pragma unroll 8
        for (int kk = 0; kk < 64; ++kk) {
            const float4 wv = *reinterpret_cast<const float4*>(&pool[2048 + kk * 64 + f4]);
            #pragma unroll
            for (int r = 0; r < 2; ++r) {
                const float iv = pool[(i2 + r) * 64 + kk];
                c[r][0] = fmaf(iv, wv.x, c[r][0]);
                c[r][1] = fmaf(iv, wv.y, c[r][1]);
                c[r][2] = fmaf(iv, wv.z, c[r][2]);
                c[r][3] = fmaf(iv, wv.w, c[r][3]);
            }
        }
    }

    // g_hf32 (tf32-rounded)
    #pragma unroll
    for (int r = 0; r < 2; ++r) {
        float4 v;
        v.x = tf32r(c[r][0]); v.y = tf32r(c[r][1]);
        v.z = tf32r(c[r][2]); v.w = tf32r(c[r][3]);
        *reinterpret_cast<float4*>(g_hf32 + (size_t)(i0 + i2 + r) * FOUT + f4) = v;
    }

    // stage fp32 h into padded smem for exact s1/s2
    __syncthreads();
    #pragma unroll
    for (int r = 0; r < 2; ++r) {
        float* row = &pool[(i2 + r) * 65 + f4];
        row[0] = c[r][0]; row[1] = c[r][1]; row[2] = c[r][2]; row[3] = c[r][3];
    }
    __syncthreads();

    if (t < 32) {
        float s1 = 0.f, s2 = 0.f;
        #pragma unroll 8
        for (int f = 0; f < 64; ++f) {
            const float hv = pool[t * 65 + f];
            s1 = fmaf(hv, __ldg(&a[f]), s1);
            s2 = fmaf(hv, __ldg(&a[64 + f]), s2);
        }
        g_s1[i0 + t] = s1 * LOG2E;
        g_s2[i0 + t] = s2 * LOG2E;
    }
}

// ============================================================================
// Kernel 2: persistent tf32 HMMA GEMM over 512 work units (atomic queue).
// Per unit: (it, js) -> D_part[js][it*128.. ][0..64] and l partials.
// ============================================================================
__global__ __launch_bounds__(256, 2) void k_mma(const int* __restrict__ adj)
{
    extern __shared__ float dsm[];
    float* As  = dsm;                  // [128][68]
    float* Bs  = dsm + SM_B_OFF;       // [64][72]
    float* s2s = dsm + SM_S2_OFF;      // [1024]
    __shared__ int s_u;

    const int t = threadIdx.x;
    const int w = t >> 5;
    const int l = t & 31;
    const int gid = l >> 2;
    const int tig = l & 3;
    const int r0 = w * 16 + gid;      // fragment rows owned by this lane
    const int r1 = r0 + 8;

    // build mapping: 2 threads per i-row, 32 j each
    const int half = l >> 4;
    const int jq   = (l & 15) * 4;

    // B staging mapping
    const int jr = t >> 2;
    const int q0 = t & 3;

    for (;;) {
        if (t == 0) s_u = atomicAdd(&g_ctr, 1);
        __syncthreads();
        const int u = s_u;
        if (u >= NUNITS) break;

        const int it = u >> 3;
        const int js = u & 7;
        const int i0 = it * TM;
        const int j0 = js * KCHUNK;

        // stage prescaled s2 chunk
        for (int k = t; k < KCHUNK; k += 256)
            s2s[k] = g_s2[j0 + k];

        int   rowk[8];
        float s1r[8];
        float l_acc[8];
        const int* aptr[8];
        int4 pre[8];
        #pragma unroll
        for (int k = 0; k < 8; ++k) {
            rowk[k]  = 2 * (w + 8 * k) + half;
            s1r[k]   = g_s1[i0 + rowk[k]];
            l_acc[k] = 0.f;
            aptr[k]  = adj + (size_t)(i0 + rowk[k]) * N_NODES + (j0 + jq);
            pre[k]   = *reinterpret_cast<const int4*>(aptr[k]);
        }

        const float s1p0 = g_s1[i0 + r0];
        const float s1p1 = g_s1[i0 + r1];
        (void)s1p0; (void)s1p1;

        float c[8][4];
        #pragma unroll
        for (int nt = 0; nt < 8; ++nt) {
            c[nt][0] = 0.f; c[nt][1] = 0.f; c[nt][2] = 0.f; c[nt][3] = 0.f;
        }
        float l0 = 0.f, l1 = 0.f;
        (void)l0; (void)l1;

        __syncthreads();   // s2s ready; As/Bs free (prev unit done)

        for (int tile = 0; tile < NT; ++tile) {
            const int jt = tile * TKJ;   // local j offset

            // --- build A (weights, tf32-rounded) into As ---
            const float4 s2q = *reinterpret_cast<const float4*>(s2s + jt + jq);
            #pragma unroll
            for (int k = 0; k < 8; ++k) {
                const int4 av = pre[k];
                if (tile + 1 < NT)
                    pre[k] = *reinterpret_cast<const int4*>(aptr[k] + (tile + 1) * TKJ);

                float x, wv;
                uint32_t p0, p1, p2, p3;
                x = s1r[k] + s2q.x;
                wv = (av.x > 0) ? ex2(fmaxf(x, 0.2f * x)) : EXP_M10;
                asm("cvt.rna.tf32.f32 %0, %1;" : "=r"(p0) : "f"(wv));
                x = s1r[k] + s2q.y;
                wv = (av.y > 0) ? ex2(fmaxf(x, 0.2f * x)) : EXP_M10;
                asm("cvt.rna.tf32.f32 %0, %1;" : "=r"(p1) : "f"(wv));
                x = s1r[k] + s2q.z;
                wv = (av.z > 0) ? ex2(fmaxf(x, 0.2f * x)) : EXP_M10;
                asm("cvt.rna.tf32.f32 %0, %1;" : "=r"(p2) : "f"(wv));
                x = s1r[k] + s2q.w;
                wv = (av.w > 0) ? ex2(fmaxf(x, 0.2f * x)) : EXP_M10;
                asm("cvt.rna.tf32.f32 %0, %1;" : "=r"(p3) : "f"(wv));

                const float f0 = __uint_as_float(p0), f1 = __uint_as_float(p1);
                const float f2 = __uint_as_float(p2), f3 = __uint_as_float(p3);
                l_acc[k] += (f0 + f1) + (f2 + f3);

                float4 v; v.x = f0; v.y = f1; v.z = f2; v.w = f3;
                *reinterpret_cast<float4*>(As + rowk[k] * A_STRIDE + jq) = v;
            }

            // --- stage B tile [64 j][64 f] ---
            {
                const float* src = g_hf32 + (size_t)(j0 + jt + jr) * FOUT;
                float* dst = Bs + jr * B_STRIDE;
                #pragma unroll
                for (int r2 = 0; r2 < 4; ++r2) {
                    const int cq = q0 * 4 + r2 * 16;
                    *reinterpret_cast<float4*>(dst + cq) =
                        *reinterpret_cast<const float4*>(src + cq);
                }
            }

            __syncthreads();

            // --- mma phase: 8 k-steps x 8 n-tiles ---
            #pragma unroll
            for (int ks = 0; ks < 8; ++ks) {
                const int k0 = ks * 8;
                const float* arow = As + (w * 16 + gid) * A_STRIDE + k0 + tig;
                const uint32_t a0 = __float_as_uint(arow[0]);
                const uint32_t a1 = __float_as_uint(arow[8 * A_STRIDE]);
                const uint32_t a2 = __float_as_uint(arow[4]);
                const uint32_t a3 = __float_as_uint(arow[8 * A_STRIDE + 4]);
                const float* brow = Bs + (k0 + tig) * B_STRIDE + gid;
                #pragma unroll
                for (int nt = 0; nt < 8; ++nt) {
                    const uint32_t b0 = __float_as_uint(brow[nt * 8]);
                    const uint32_t b1 = __float_as_uint(brow[4 * B_STRIDE + nt * 8]);
                    mma_tf32(c[nt], a0, a1, a2, a3, b0, b1);
                }
            }

            __syncthreads();
        }

        // --- epilogue: write D partials ---
        #pragma unroll
        for (int nt = 0; nt < 8; ++nt) {
            const int col = nt * 8 + tig * 2;
            float* p0 = &g_part[js][i0 + r0][col];
            float* p1 = &g_part[js][i0 + r1][col];
            *reinterpret_cast<float2*>(p0) = make_float2(c[nt][0], c[nt][1]);
            *reinterpret_cast<float2*>(p1) = make_float2(c[nt][2], c[nt][3]);
        }

        // --- l partials: reduce over the 16 lanes (jq groups) sharing each row ---
        #pragma unroll
        for (int k = 0; k < 8; ++k) {
            float v = l_acc[k];
            v += __shfl_xor_sync(0xffffffffu, v, 1);
            v += __shfl_xor_sync(0xffffffffu, v, 2);
            v += __shfl_xor_sync(0xffffffffu, v, 4);
            v += __shfl_xor_sync(0xffffffffu, v, 8);
            if ((l & 15) == 0) g_lpart[js][i0 + rowk[k]] = v;
        }

        __syncthreads();   // all done with s_u/smem before next unit claim
    }
}

// ============================================================================
// Kernel 3: reduce 8 partials, normalize, ELU
// ============================================================================
__global__ __launch_bounds__(256) void k_reduce(float* __restrict__ out)
{
    const int idx = blockIdx.x * 256 + threadIdx.x;   // over N*FOUT
    const int i = idx >> 6;
    const int f = idx & 63;

    float s = 0.0f, lsum = 0.0f;
    #pragma unroll
    for (int p = 0; p < JSPLIT; ++p) {
        s    += g_part[p][i][f];
        lsum += g_lpart[p][i];
    }
    const float v = s / lsum;
    out[idx] = (v > 0.0f) ? v : (__expf(v) - 1.0f);
}

// ============================================================================
extern "C" void kernel_launch(void* const* d_in, const int* in_sizes, int n_in,
                              void* d_out, int out_size)
{
    const float* input = (const float*)d_in[0];  // [8192, 256]
    const int*   adj   = (const int*)  d_in[1];  // [8192, 8192]
    const float* W     = (const float*)d_in[2];  // [256, 64]
    const float* a     = (const float*)d_in[3];  // [128, 1]
    float* out = (float*)d_out;                  // [8192, 64]

    cudaFuncSetAttribute(k_mma, cudaFuncAttributeMaxDynamicSharedMemorySize, SMEM_BYTES);

    k_h<<<N_NODES / 32, 256>>>(input, W, a);
    k_mma<<<GRID_MMA, 256, SMEM_BYTES>>>(adj);
    k_reduce<<<(N_NODES * FOUT) / 256, 256>>>(out);
}

// round 9
// speedup vs baseline: 1.5264x; 1.3894x over previous
#include <cuda_runtime.h>
#include <cstdint>

#define N_NODES 8192
#define FIN 256
#define FOUT 64
#define LOG2E 1.4426950408889634f
#define NEG10L2E (-14.426950408889634f)

// ---- k_mma geometry ----
#define TM 128
#define TKJ 64
#define JSPLIT 32
#define KCHUNK (N_NODES / JSPLIT)    // 256
#define NT (KCHUNK / TKJ)            // 4

// ---- scratch (allocation-free rule) ----
__device__ float g_s1[N_NODES];                    // prescaled by LOG2E
__device__ float g_s2[N_NODES];                    // prescaled by LOG2E
__device__ uint2 g_hp[(N_NODES / 16) * 256 / 64 * 64]; // fragment-packed fp16 h, 1 MB
__device__ float g_part[JSPLIT][N_NODES][FOUT];    // 64 MB
__device__ float g_lpart[JSPLIT][N_NODES];         // 1 MB
__device__ unsigned g_s2key = 0u;                  // ordered-key max of s2' (idempotent)

__device__ __forceinline__ unsigned fenc(float f) {
    unsigned u = __float_as_uint(f);
    return u ^ ((unsigned)((int)u >> 31) | 0x80000000u);
}
__device__ __forceinline__ float fdec(unsigned u) {
    unsigned b = (u & 0x80000000u) ? (u ^ 0x80000000u) : ~u;
    return __uint_as_float(b);
}
__device__ __forceinline__ float ex2(float x) {
    float r;
    asm("ex2.approx.f32 %0, %1;" : "=f"(r) : "f"(x));
    return r;
}
__device__ __forceinline__ uint32_t packh2(float lo, float hi) {
    uint32_t r;
    asm("cvt.rn.f16x2.f32 %0, %1, %2;" : "=r"(r) : "f"(hi), "f"(lo));
    return r;
}
__device__ __forceinline__ void mma_fp16(float c[4],
    uint32_t a0, uint32_t a1, uint32_t a2, uint32_t a3,
    uint32_t b0, uint32_t b1)
{
    asm volatile(
        "mma.sync.aligned.m16n8k16.row.col.f32.f16.f16.f32 "
        "{%0,%1,%2,%3}, {%4,%5,%6,%7}, {%8,%9}, {%0,%1,%2,%3};"
        : "+f"(c[0]), "+f"(c[1]), "+f"(c[2]), "+f"(c[3])
        : "r"(a0), "r"(a1), "r"(a2), "r"(a3), "r"(b0), "r"(b1));
}
// weight in log2 domain: lrelu2 - m2 folded into per-row consts
__device__ __forceinline__ float wgt(float s1a, float s1b, float mc,
                                     float s2, int av) {
    const float t1 = s1a + s2;
    const float t2 = fmaf(0.2f, s2, s1b);
    float y = fmaxf(t1, t2);
    y = (av > 0) ? y : mc;
    return ex2(y);
}

// ============================================================================
// Kernel 1: h = input @ W; emit prescaled s1,s2; fp16 fragment-packed h;
// atomicMax of s2'. Grid: 512 blocks x 16 rows, 256 threads.
// ============================================================================
__global__ __launch_bounds__(256) void k_h(
    const float* __restrict__ input,   // [N, FIN]
    const float* __restrict__ W,       // [FIN, FOUT]
    const float* __restrict__ a)       // [2*FOUT]
{
    __shared__ float in_s[16 * 64];    // 4 KB
    __shared__ float w_s[64 * 64];     // 16 KB
    __shared__ float h_s[16 * 68];     // padded

    const int t = threadIdx.x;
    const int i0 = blockIdx.x * 16;
    const int row = t >> 4;
    const int f4 = (t & 15) * 4;

    float c0 = 0.f, c1 = 0.f, c2 = 0.f, c3 = 0.f;
    const float4* in4 = reinterpret_cast<const float4*>(input);
    const float4* W4  = reinterpret_cast<const float4*>(W);

    for (int kc = 0; kc < 4; ++kc) {
        __syncthreads();
        reinterpret_cast<float4*>(in_s)[t] =
            in4[(size_t)(i0 + (t >> 4)) * 64 + kc * 16 + (t & 15)];
        #pragma unroll
        for (int r2 = 0; r2 < 4; ++r2) {
            const int idx = t + r2 * 256;
            reinterpret_cast<float4*>(w_s)[idx] =
                W4[(size_t)(kc * 64 + (idx >> 4)) * 16 + (idx & 15)];
        }
        __syncthreads();
        #pragma unroll 8
        for (int kk = 0; kk < 64; ++kk) {
            const float4 wv = *reinterpret_cast<const float4*>(&w_s[kk * 64 + f4]);
            const float iv = in_s[row * 64 + kk];
            c0 = fmaf(iv, wv.x, c0);
            c1 = fmaf(iv, wv.y, c1);
            c2 = fmaf(iv, wv.z, c2);
            c3 = fmaf(iv, wv.w, c3);
        }
    }

    __syncthreads();
    {
        float4 v; v.x = c0; v.y = c1; v.z = c2; v.w = c3;
        *reinterpret_cast<float4*>(&h_s[row * 68 + f4]) = v;
    }
    __syncthreads();

    if (t < 16) {
        float s1 = 0.f, s2 = 0.f;
        #pragma unroll 8
        for (int f = 0; f < 64; ++f) {
            const float hv = h_s[t * 68 + f];
            s1 = fmaf(hv, __ldg(&a[f]), s1);
            s2 = fmaf(hv, __ldg(&a[64 + f]), s2);
        }
        g_s1[i0 + t] = s1 * LOG2E;
        const float s2p = s2 * LOG2E;
        g_s2[i0 + t] = s2p;
        float m = s2p;
        #pragma unroll
        for (int d = 8; d; d >>= 1)
            m = fmaxf(m, __shfl_xor_sync(0x0000ffffu, m, d));
        if (t == 0) atomicMax(&g_s2key, fenc(m));
    }

    // fragment-packed fp16 h: g_hp[block][q][f].x = (h[2q],h[2q+1]),
    //                                       .y = (h[2q+8],h[2q+9])
    {
        const int q = t >> 6;
        const int f = t & 63;
        const float lo0 = h_s[(2 * q) * 68 + f];
        const float lo1 = h_s[(2 * q + 1) * 68 + f];
        const float hi0 = h_s[(2 * q + 8) * 68 + f];
        const float hi1 = h_s[(2 * q + 9) * 68 + f];
        uint2 v;
        v.x = packh2(lo0, lo1);
        v.y = packh2(hi0, hi1);
        g_hp[blockIdx.x * 256 + q * 64 + f] = v;
    }
}

// ============================================================================
// Kernel 2: fused fp16 HMMA GEMM — A fragments built in registers from adj,
// B staged from pre-packed g_hp (double-buffered). Grid (64, 32), 256 thr.
// ============================================================================
__global__ __launch_bounds__(256, 2) void k_mma(const int* __restrict__ adj)
{
    __shared__ float s2s[KCHUNK];                      // 1 KB
    __shared__ __align__(16) uint2 Bs[2][16][68];      // 17 KB

    const int t = threadIdx.x;
    const int w = t >> 5;
    const int l = t & 31;
    const int gid = l >> 2;
    const int tig = l & 3;
    const int i0 = blockIdx.x * TM;
    const int js = blockIdx.y;
    const int j0 = js * KCHUNK;
    const int r0 = w * 16 + gid;
    const int r1 = r0 + 8;

    // stage s2 chunk (exactly 256 threads)
    s2s[t] = g_s2[j0 + t];

    // per-row constants (log2-domain, with overflow-bound m2 folded in)
    const float s2m = fdec(g_s2key);
    float s1a0, s1b0, mc0, s1a1, s1b1, mc1, m20, m21;
    {
        const float s1r = g_s1[i0 + r0];
        const float tt = s1r + s2m;
        m20 = fmaxf(fmaxf(tt, 0.2f * tt), NEG10L2E);
        s1a0 = s1r - m20;
        s1b0 = 0.2f * s1r - m20;
        mc0 = NEG10L2E - m20;
    }
    {
        const float s1r = g_s1[i0 + r1];
        const float tt = s1r + s2m;
        m21 = fmaxf(fmaxf(tt, 0.2f * tt), NEG10L2E);
        s1a1 = s1r - m21;
        s1b1 = 0.2f * s1r - m21;
        mc1 = NEG10L2E - m21;
    }

    const int2* a0p = reinterpret_cast<const int2*>(
        adj + (size_t)(i0 + r0) * N_NODES + j0);
    const int2* a1p = reinterpret_cast<const int2*>(
        adj + (size_t)(i0 + r1) * N_NODES + j0);

    float c[8][4];
    #pragma unroll
    for (int nt = 0; nt < 8; ++nt) {
        c[nt][0] = 0.f; c[nt][1] = 0.f; c[nt][2] = 0.f; c[nt][3] = 0.f;
    }
    float lac0 = 0.f, lac1 = 0.f;

    // stage B tile 0 into buffer 0
    {
        const uint4* src = reinterpret_cast<const uint4*>(g_hp) + ((size_t)j0 >> 4) * 128;
        const uint4 e0 = __ldg(&src[t]);
        const uint4 e1 = __ldg(&src[t + 256]);
        *reinterpret_cast<uint4*>(&Bs[0][t >> 5][(2 * t) & 63]) = e0;
        *reinterpret_cast<uint4*>(&Bs[0][(t >> 5) + 8][(2 * t) & 63]) = e1;
    }

    for (int tile = 0; tile < NT; ++tile) {
        const int buf = tile & 1;

        // adj loads for this tile (16 coalesced LDG.64 per lane-pattern)
        int2 av[4][4];
        #pragma unroll
        for (int ks = 0; ks < 4; ++ks) {
            const int base = (tile * TKJ + ks * 16) / 2 + tig;
            av[ks][0] = __ldg(a0p + base);
            av[ks][1] = __ldg(a0p + base + 4);
            av[ks][2] = __ldg(a1p + base);
            av[ks][3] = __ldg(a1p + base + 4);
        }

        __syncthreads();   // Bs[buf] staged; prior reads of Bs[buf^1] done

        // stage next tile into the other buffer
        if (tile + 1 < NT) {
            const uint4* src = reinterpret_cast<const uint4*>(g_hp) +
                               ((size_t)(j0 + (tile + 1) * TKJ) >> 4) * 128;
            const uint4 e0 = __ldg(&src[t]);
            const uint4 e1 = __ldg(&src[t + 256]);
            *reinterpret_cast<uint4*>(&Bs[buf ^ 1][t >> 5][(2 * t) & 63]) = e0;
            *reinterpret_cast<uint4*>(&Bs[buf ^ 1][(t >> 5) + 8][(2 * t) & 63]) = e1;
        }

        #pragma unroll
        for (int ks = 0; ks < 4; ++ks) {
            const int jb = tile * TKJ + ks * 16 + 2 * tig;
            const float2 sA = *reinterpret_cast<const float2*>(s2s + jb);
            const float2 sB = *reinterpret_cast<const float2*>(s2s + jb + 8);

            const float w00 = wgt(s1a0, s1b0, mc0, sA.x, av[ks][0].x);
            const float w01 = wgt(s1a0, s1b0, mc0, sA.y, av[ks][0].y);
            const float w02 = wgt(s1a0, s1b0, mc0, sB.x, av[ks][1].x);
            const float w03 = wgt(s1a0, s1b0, mc0, sB.y, av[ks][1].y);
            const float w10 = wgt(s1a1, s1b1, mc1, sA.x, av[ks][2].x);
            const float w11 = wgt(s1a1, s1b1, mc1, sA.y, av[ks][2].y);
            const float w12 = wgt(s1a1, s1b1, mc1, sB.x, av[ks][3].x);
            const float w13 = wgt(s1a1, s1b1, mc1, sB.y, av[ks][3].y);

            lac0 += (w00 + w01) + (w02 + w03);
            lac1 += (w10 + w11) + (w12 + w13);

            const uint32_t A0 = packh2(w00, w01);
            const uint32_t A1 = packh2(w10, w11);
            const uint32_t A2 = packh2(w02, w03);
            const uint32_t A3 = packh2(w12, w13);

            const uint2* brow = &Bs[buf][ks * 4 + tig][gid];
            #pragma unroll
            for (int nt = 0; nt < 8; ++nt) {
                const uint2 b = brow[nt * 8];
                mma_fp16(c[nt], A0, A1, A2, A3, b.x, b.y);
            }
        }
    }

    // epilogue: D partials (scaled by 2^-m2 per row — cancels in k_reduce)
    #pragma unroll
    for (int nt = 0; nt < 8; ++nt) {
        const int col = nt * 8 + tig * 2;
        *reinterpret_cast<float2*>(&g_part[js][i0 + r0][col]) =
            make_float2(c[nt][0], c[nt][1]);
        *reinterpret_cast<float2*>(&g_part[js][i0 + r1][col]) =
            make_float2(c[nt][2], c[nt][3]);
    }

    // l partials: reduce across the 4 tig-lanes sharing each row
    lac0 += __shfl_xor_sync(0xffffffffu, lac0, 1);
    lac0 += __shfl_xor_sync(0xffffffffu, lac0, 2);
    lac1 += __shfl_xor_sync(0xffffffffu, lac1, 1);
    lac1 += __shfl_xor_sync(0xffffffffu, lac1, 2);
    if (tig == 0) {
        g_lpart[js][i0 + r0] = lac0;
        g_lpart[js][i0 + r1] = lac1;
    }
}

// ============================================================================
// Kernel 3: reduce 32 partials, normalize, ELU. float4 per thread.
// ============================================================================
__global__ __launch_bounds__(256) void k_reduce(float* __restrict__ out)
{
    const int gi = blockIdx.x * 256 + threadIdx.x;   // over N*16
    const int i = gi >> 4;
    const int f4 = (gi & 15) * 4;

    float4 s = make_float4(0.f, 0.f, 0.f, 0.f);
    float lsum = 0.f;
    #pragma unroll
    for (int p = 0; p < JSPLIT; ++p) {
        const float4 v = *reinterpret_cast<const float4*>(&g_part[p][i][f4]);
        s.x += v.x; s.y += v.y; s.z += v.z; s.w += v.w;
        lsum += g_lpart[p][i];
    }
    const float inv = 1.0f / lsum;
    float4 o;
    o.x = s.x * inv; o.y = s.y * inv; o.z = s.z * inv; o.w = s.w * inv;
    o.x = o.x > 0.f ? o.x : (__expf(o.x) - 1.f);
    o.y = o.y > 0.f ? o.y : (__expf(o.y) - 1.f);
    o.z = o.z > 0.f ? o.z : (__expf(o.z) - 1.f);
    o.w = o.w > 0.f ? o.w : (__expf(o.w) - 1.f);
    *reinterpret_cast<float4*>(&out[(size_t)i * FOUT + f4]) = o;
}

// ============================================================================
extern "C" void kernel_launch(void* const* d_in, const int* in_sizes, int n_in,
                              void* d_out, int out_size)
{
    const float* input = (const float*)d_in[0];  // [8192, 256]
    const int*   adj   = (const int*)  d_in[1];  // [8192, 8192]
    const float* W     = (const float*)d_in[2];  // [256, 64]
    const float* a     = (const float*)d_in[3];  // [128, 1]
    float* out = (float*)d_out;                  // [8192, 64]

    k_h<<<N_NODES / 16, 256>>>(input, W, a);
    k_mma<<<dim3(N_NODES / TM, JSPLIT), 256>>>(adj);
    k_reduce<<<(N_NODES * 16) / 256, 256>>>(out);
}

// round 10
// speedup vs baseline: 1.7362x; 1.1374x over previous
#include <cuda_runtime.h>
#include <cstdint>

#define N_NODES 8192
#define FIN 256
#define FOUT 64
#define LOG2E 1.4426950408889634f
#define NEG10L2E (-14.426950408889634f)

// ---- k_mma geometry ----
#define TM 128
#define TKJ 64
#define JSPLIT 32
#define KCHUNK (N_NODES / JSPLIT)    // 256
#define NT (KCHUNK / TKJ)            // 4

// ---- scratch (allocation-free rule) ----
__device__ float g_s1[N_NODES];                    // prescaled by LOG2E
__device__ float g_s2[N_NODES];                    // prescaled by LOG2E
__device__ uint2 g_hp[(N_NODES / 16) * 256];       // fragment-packed fp16 h, 1 MB
__device__ float g_part[JSPLIT][N_NODES][FOUT];    // 64 MB
__device__ float g_lpart[JSPLIT][N_NODES];         // 1 MB
__device__ unsigned g_s2key = 0u;                  // ordered-key max of s2' (idempotent)

__device__ __forceinline__ unsigned fenc(float f) {
    unsigned u = __float_as_uint(f);
    return u ^ ((unsigned)((int)u >> 31) | 0x80000000u);
}
__device__ __forceinline__ float fdec(unsigned u) {
    unsigned b = (u & 0x80000000u) ? (u ^ 0x80000000u) : ~u;
    return __uint_as_float(b);
}
__device__ __forceinline__ float ex2(float x) {
    float r;
    asm("ex2.approx.f32 %0, %1;" : "=f"(r) : "f"(x));
    return r;
}
__device__ __forceinline__ uint32_t packh2(float lo, float hi) {
    uint32_t r;
    asm("cvt.rn.f16x2.f32 %0, %1, %2;" : "=r"(r) : "f"(hi), "f"(lo));
    return r;
}
__device__ __forceinline__ void mma_fp16(float c[4],
    uint32_t a0, uint32_t a1, uint32_t a2, uint32_t a3,
    uint32_t b0, uint32_t b1)
{
    asm volatile(
        "mma.sync.aligned.m16n8k16.row.col.f32.f16.f16.f32 "
        "{%0,%1,%2,%3}, {%4,%5,%6,%7}, {%8,%9}, {%0,%1,%2,%3};"
        : "+f"(c[0]), "+f"(c[1]), "+f"(c[2]), "+f"(c[3])
        : "r"(a0), "r"(a1), "r"(a2), "r"(a3), "r"(b0), "r"(b1));
}
// weight in log2 domain: lrelu2 - m2 folded into per-row consts
__device__ __forceinline__ float wgt(float s1a, float s1b, float mc,
                                     float s2, int av) {
    const float t1 = s1a + s2;
    const float t2 = fmaf(0.2f, s2, s1b);
    float y = fmaxf(t1, t2);
    y = (av > 0) ? y : mc;
    return ex2(y);
}

// ============================================================================
// Kernel 1: h = input @ W (64-row tiles, W loaded once per CTA); emit
// prescaled s1,s2, atomicMax of s2', and pi-permuted fp16 B fragments.
// Grid: 128 blocks x 64 rows, 256 threads.
// ============================================================================
__global__ __launch_bounds__(256) void k_h(
    const float* __restrict__ input,   // [N, FIN]
    const float* __restrict__ W,       // [FIN, FOUT]
    const float* __restrict__ a)       // [2*FOUT]
{
    __shared__ float pool[8192];       // in_s[64][64] @0 | w_s[64][64] @4096
    const int t = threadIdx.x;
    const int i0 = blockIdx.x * 64;
    const int f4 = (t & 15) * 4;
    const int i4 = (t >> 4) * 4;

    float c[4][4];
    #pragma unroll
    for (int r = 0; r < 4; ++r) { c[r][0]=0.f; c[r][1]=0.f; c[r][2]=0.f; c[r][3]=0.f; }

    const float4* in4 = reinterpret_cast<const float4*>(input);
    const float4* W4  = reinterpret_cast<const float4*>(W);

    for (int kc = 0; kc < 4; ++kc) {
        __syncthreads();
        #pragma unroll
        for (int r = 0; r < 4; ++r) {
            const int idx = t + r * 256;
            const int row = idx >> 4;
            const int c4  = idx & 15;
            *reinterpret_cast<float4*>(&pool[row * 64 + c4 * 4]) =
                in4[(size_t)(i0 + row) * 64 + kc * 16 + c4];
            *reinterpret_cast<float4*>(&pool[4096 + row * 64 + c4 * 4]) =
                W4[(size_t)(kc * 64 + row) * 16 + c4];
        }
        __syncthreads();
        #pragma unroll 8
        for (int kk = 0; kk < 64; ++kk) {
            const float4 wv = *reinterpret_cast<const float4*>(&pool[4096 + kk * 64 + f4]);
            #pragma unroll
            for (int r = 0; r < 4; ++r) {
                const float iv = pool[(i4 + r) * 64 + kk];
                c[r][0] = fmaf(iv, wv.x, c[r][0]);
                c[r][1] = fmaf(iv, wv.y, c[r][1]);
                c[r][2] = fmaf(iv, wv.z, c[r][2]);
                c[r][3] = fmaf(iv, wv.w, c[r][3]);
            }
        }
    }

    // stage fp32 h into padded smem h_s[64][65]
    __syncthreads();
    #pragma unroll
    for (int r = 0; r < 4; ++r) {
        float* row = &pool[(i4 + r) * 65 + f4];
        row[0] = c[r][0]; row[1] = c[r][1]; row[2] = c[r][2]; row[3] = c[r][3];
    }
    __syncthreads();

    // s1 / s2 (exact fp32), prescaled by log2(e); chip-wide max of s2'
    if (t < 64) {
        float s1 = 0.f, s2 = 0.f;
        #pragma unroll 8
        for (int f = 0; f < 64; ++f) {
            const float hv = pool[t * 65 + f];
            s1 = fmaf(hv, __ldg(&a[f]), s1);
            s2 = fmaf(hv, __ldg(&a[64 + f]), s2);
        }
        g_s1[i0 + t] = s1 * LOG2E;
        const float s2p = s2 * LOG2E;
        g_s2[i0 + t] = s2p;
        float m = s2p;
        #pragma unroll
        for (int d = 16; d; d >>= 1)
            m = fmaxf(m, __shfl_xor_sync(0xffffffffu, m, d));
        if ((t & 31) == 0) atomicMax(&g_s2key, fenc(m));
    }

    // pi-permuted fragment-packed fp16 h:
    // per 16-row block, entry (q,f): .x=(h[4q],h[4q+1]), .y=(h[4q+2],h[4q+3])
    #pragma unroll
    for (int e = 0; e < 4; ++e) {
        const int idx = t + e * 256;        // 0..1023
        const int blk = idx >> 8;           // 0..3
        const int q   = (idx >> 6) & 3;
        const int f   = idx & 63;
        const int rb  = blk * 16 + 4 * q;
        uint2 v;
        v.x = packh2(pool[(rb + 0) * 65 + f], pool[(rb + 1) * 65 + f]);
        v.y = packh2(pool[(rb + 2) * 65 + f], pool[(rb + 3) * 65 + f]);
        g_hp[((i0 >> 4) + blk) * 256 + q * 64 + f] = v;
    }
}

// ============================================================================
// Kernel 2: fused fp16 HMMA GEMM — A fragments built in registers from adj
// (pi-permuted: lane tig owns j 4tig..4tig+3, contiguous int4 loads),
// B staged from pre-packed g_hp (double-buffered). Grid (64, 32), 256 thr.
// ============================================================================
__global__ __launch_bounds__(256, 2) void k_mma(const int* __restrict__ adj)
{
    __shared__ float s2s[KCHUNK];                      // 1 KB
    __shared__ __align__(16) uint2 Bs[2][16][68];      // 17 KB

    const int t = threadIdx.x;
    const int w = t >> 5;
    const int l = t & 31;
    const int gid = l >> 2;
    const int tig = l & 3;
    const int i0 = blockIdx.x * TM;
    const int js = blockIdx.y;
    const int j0 = js * KCHUNK;
    const int r0 = w * 16 + gid;
    const int r1 = r0 + 8;

    // stage s2 chunk (exactly 256 threads)
    s2s[t] = g_s2[j0 + t];

    // per-row constants (log2-domain, with overflow-bound m2 folded in)
    const float s2m = fdec(g_s2key);
    float s1a0, s1b0, mc0, s1a1, s1b1, mc1;
    {
        const float s1r = g_s1[i0 + r0];
        const float tt = s1r + s2m;
        const float m2 = fmaxf(fmaxf(tt, 0.2f * tt), NEG10L2E);
        s1a0 = s1r - m2;
        s1b0 = 0.2f * s1r - m2;
        mc0 = NEG10L2E - m2;
    }
    {
        const float s1r = g_s1[i0 + r1];
        const float tt = s1r + s2m;
        const float m2 = fmaxf(fmaxf(tt, 0.2f * tt), NEG10L2E);
        s1a1 = s1r - m2;
        s1b1 = 0.2f * s1r - m2;
        mc1 = NEG10L2E - m2;
    }

    const int4* a0p = reinterpret_cast<const int4*>(
        adj + (size_t)(i0 + r0) * N_NODES + j0) + tig;
    const int4* a1p = reinterpret_cast<const int4*>(
        adj + (size_t)(i0 + r1) * N_NODES + j0) + tig;

    float c[8][4];
    #pragma unroll
    for (int nt = 0; nt < 8; ++nt) {
        c[nt][0] = 0.f; c[nt][1] = 0.f; c[nt][2] = 0.f; c[nt][3] = 0.f;
    }
    float lac0 = 0.f, lac1 = 0.f;

    // stage B tile 0 into buffer 0
    {
        const uint4* src = reinterpret_cast<const uint4*>(g_hp) + ((size_t)j0 >> 4) * 128;
        const uint4 e0 = __ldg(&src[t]);
        const uint4 e1 = __ldg(&src[t + 256]);
        *reinterpret_cast<uint4*>(&Bs[0][t >> 5][(2 * t) & 63]) = e0;
        *reinterpret_cast<uint4*>(&Bs[0][(t >> 5) + 8][(2 * t) & 63]) = e1;
    }

    for (int tile = 0; tile < NT; ++tile) {
        const int buf = tile & 1;

        // adj loads for this tile: 8 LDG.128, contiguous 64B per row per quad
        int4 av0[4], av1[4];
        #pragma unroll
        for (int ks = 0; ks < 4; ++ks) {
            av0[ks] = __ldg(a0p + tile * 16 + ks * 4);
            av1[ks] = __ldg(a1p + tile * 16 + ks * 4);
        }

        __syncthreads();   // Bs[buf] staged; prior reads of Bs[buf^1] done

        // stage next tile into the other buffer
        if (tile + 1 < NT) {
            const uint4* src = reinterpret_cast<const uint4*>(g_hp) +
                               ((size_t)(j0 + (tile + 1) * TKJ) >> 4) * 128;
            const uint4 e0 = __ldg(&src[t]);
            const uint4 e1 = __ldg(&src[t + 256]);
            *reinterpret_cast<uint4*>(&Bs[buf ^ 1][t >> 5][(2 * t) & 63]) = e0;
            *reinterpret_cast<uint4*>(&Bs[buf ^ 1][(t >> 5) + 8][(2 * t) & 63]) = e1;
        }

        #pragma unroll
        for (int ks = 0; ks < 4; ++ks) {
            const float4 s4 = *reinterpret_cast<const float4*>(
                s2s + tile * TKJ + ks * 16 + 4 * tig);

            const float w00 = wgt(s1a0, s1b0, mc0, s4.x, av0[ks].x);
            const float w01 = wgt(s1a0, s1b0, mc0, s4.y, av0[ks].y);
            const float w02 = wgt(s1a0, s1b0, mc0, s4.z, av0[ks].z);
            const float w03 = wgt(s1a0, s1b0, mc0, s4.w, av0[ks].w);
            const float w10 = wgt(s1a1, s1b1, mc1, s4.x, av1[ks].x);
            const float w11 = wgt(s1a1, s1b1, mc1, s4.y, av1[ks].y);
            const float w12 = wgt(s1a1, s1b1, mc1, s4.z, av1[ks].z);
            const float w13 = wgt(s1a1, s1b1, mc1, s4.w, av1[ks].w);

            lac0 += (w00 + w01) + (w02 + w03);
            lac1 += (w10 + w11) + (w12 + w13);

            // pi-permuted fragment slots: a0=(j 4tig,4tig+1) r0, a2=(4tig+2,+3) r0
            const uint32_t A0 = packh2(w00, w01);
            const uint32_t A1 = packh2(w10, w11);
            const uint32_t A2 = packh2(w02, w03);
            const uint32_t A3 = packh2(w12, w13);

            const uint2* brow = &Bs[buf][ks * 4 + tig][gid];
            #pragma unroll
            for (int nt = 0; nt < 8; ++nt) {
                const uint2 b = brow[nt * 8];
                mma_fp16(c[nt], A0, A1, A2, A3, b.x, b.y);
            }
        }
    }

    // epilogue: D partials (scaled by 2^-m2 per row — cancels in k_reduce)
    #pragma unroll
    for (int nt = 0; nt < 8; ++nt) {
        const int col = nt * 8 + tig * 2;
        *reinterpret_cast<float2*>(&g_part[js][i0 + r0][col]) =
            make_float2(c[nt][0], c[nt][1]);
        *reinterpret_cast<float2*>(&g_part[js][i0 + r1][col]) =
            make_float2(c[nt][2], c[nt][3]);
    }

    // l partials: reduce across the 4 tig-lanes sharing each row
    lac0 += __shfl_xor_sync(0xffffffffu, lac0, 1);
    lac0 += __shfl_xor_sync(0xffffffffu, lac0, 2);
    lac1 += __shfl_xor_sync(0xffffffffu, lac1, 1);
    lac1 += __shfl_xor_sync(0xffffffffu, lac1, 2);
    if (tig == 0) {
        g_lpart[js][i0 + r0] = lac0;
        g_lpart[js][i0 + r1] = lac1;
    }
}

// ============================================================================
// Kernel 3: reduce 32 partials, normalize, ELU. float4 per thread.
// ============================================================================
__global__ __launch_bounds__(256) void k_reduce(float* __restrict__ out)
{
    const int gi = blockIdx.x * 256 + threadIdx.x;   // over N*16
    const int i = gi >> 4;
    const int f4 = (gi & 15) * 4;

    float4 s = make_float4(0.f, 0.f, 0.f, 0.f);
    float lsum = 0.f;
    #pragma unroll
    for (int p = 0; p < JSPLIT; ++p) {
        const float4 v = *reinterpret_cast<const float4*>(&g_part[p][i][f4]);
        s.x += v.x; s.y += v.y; s.z += v.z; s.w += v.w;
        lsum += g_lpart[p][i];
    }
    const float inv = 1.0f / lsum;
    float4 o;
    o.x = s.x * inv; o.y = s.y * inv; o.z = s.z * inv; o.w = s.w * inv;
    o.x = o.x > 0.f ? o.x : (__expf(o.x) - 1.f);
    o.y = o.y > 0.f ? o.y : (__expf(o.y) - 1.f);
    o.z = o.z > 0.f ? o.z : (__expf(o.z) - 1.f);
    o.w = o.w > 0.f ? o.w : (__expf(o.w) - 1.f);
    *reinterpret_cast<float4*>(&out[(size_t)i * FOUT + f4]) = o;
}

// ============================================================================
extern "C" void kernel_launch(void* const* d_in, const int* in_sizes, int n_in,
                              void* d_out, int out_size)
{
    const float* input = (const float*)d_in[0];  // [8192, 256]
    const int*   adj   = (const int*)  d_in[1];  // [8192, 8192]
    const float* W     = (const float*)d_in[2];  // [256, 64]
    const float* a     = (const float*)d_in[3];  // [128, 1]
    float* out = (float*)d_out;                  // [8192, 64]

    k_h<<<N_NODES / 64, 256>>>(input, W, a);
    k_mma<<<dim3(N_NODES / TM, JSPLIT), 256>>>(adj);
    k_reduce<<<(N_NODES * 16) / 256, 256>>>(out);
}

// round 11
// speedup vs baseline: 1.9048x; 1.0971x over previous
#include <cuda_runtime.h>
#include <cstdint>

#define N_NODES 8192
#define FIN 256
#define FOUT 64
#define LOG2E 1.4426950408889634f
#define NEG10L2E (-14.426950408889634f)

// ---- k_mma geometry ----
#define TM 128
#define TKJ 64
#define JSPLIT 16
#define KCHUNK (N_NODES / JSPLIT)    // 512
#define NT (KCHUNK / TKJ)            // 8

// ---- scratch (allocation-free rule) ----
__device__ float g_s1[N_NODES];                    // prescaled by LOG2E
__device__ float g_s2[N_NODES];                    // prescaled by LOG2E
__device__ uint2 g_hp[(N_NODES / 16) * 256];       // fragment-packed fp16 h, 1 MB
__device__ float g_part[JSPLIT][N_NODES][FOUT];    // 32 MB
__device__ float g_lpart[JSPLIT][N_NODES];         // 512 KB
__device__ unsigned g_s2key = 0u;                  // ordered-key max of s2' (idempotent)

__device__ __forceinline__ unsigned fenc(float f) {
    unsigned u = __float_as_uint(f);
    return u ^ ((unsigned)((int)u >> 31) | 0x80000000u);
}
__device__ __forceinline__ float fdec(unsigned u) {
    unsigned b = (u & 0x80000000u) ? (u ^ 0x80000000u) : ~u;
    return __uint_as_float(b);
}
__device__ __forceinline__ float ex2(float x) {
    float r;
    asm("ex2.approx.f32 %0, %1;" : "=f"(r) : "f"(x));
    return r;
}
__device__ __forceinline__ uint32_t packh2(float lo, float hi) {
    uint32_t r;
    asm("cvt.rn.f16x2.f32 %0, %1, %2;" : "=r"(r) : "f"(hi), "f"(lo));
    return r;
}
__device__ __forceinline__ void mma_fp16(float c[4],
    uint32_t a0, uint32_t a1, uint32_t a2, uint32_t a3,
    uint32_t b0, uint32_t b1)
{
    asm volatile(
        "mma.sync.aligned.m16n8k16.row.col.f32.f16.f16.f32 "
        "{%0,%1,%2,%3}, {%4,%5,%6,%7}, {%8,%9}, {%0,%1,%2,%3};"
        : "+f"(c[0]), "+f"(c[1]), "+f"(c[2]), "+f"(c[3])
        : "r"(a0), "r"(a1), "r"(a2), "r"(a3), "r"(b0), "r"(b1));
}
// weight in log2 domain: lrelu2 - m2 folded into per-row consts
__device__ __forceinline__ float wgt(float s1a, float s1b, float mc,
                                     float s2, int av) {
    const float t1 = s1a + s2;
    const float t2 = fmaf(0.2f, s2, s1b);
    float y = fmaxf(t1, t2);
    y = (av > 0) ? y : mc;
    return ex2(y);
}

// ============================================================================
// Kernel 1: h = input @ W (64-row tiles, W loaded once per CTA, 512 threads
// for latency hiding); emit prescaled s1,s2, s2'-max, pi-permuted fp16 B.
// Grid: 128 blocks x 64 rows.
// ============================================================================
__global__ __launch_bounds__(512) void k_h(
    const float* __restrict__ input,   // [N, FIN]
    const float* __restrict__ W,       // [FIN, FOUT]
    const float* __restrict__ a)       // [2*FOUT]
{
    __shared__ float pool[8192];       // in_s[64][64] @0 | w_s[64][64] @4096
    const int t = threadIdx.x;         // 0..511
    const int i0 = blockIdx.x * 64;
    const int f4 = (t & 15) * 4;
    const int i2 = (t >> 4) * 2;       // 2 rows per thread

    float c[2][4];
    #pragma unroll
    for (int r = 0; r < 2; ++r) { c[r][0]=0.f; c[r][1]=0.f; c[r][2]=0.f; c[r][3]=0.f; }

    const float4* in4 = reinterpret_cast<const float4*>(input);
    const float4* W4  = reinterpret_cast<const float4*>(W);

    for (int kc = 0; kc < 4; ++kc) {
        __syncthreads();
        #pragma unroll
        for (int r = 0; r < 2; ++r) {
            const int idx = t + r * 512;
            const int row = idx >> 4;
            const int c4  = idx & 15;
            *reinterpret_cast<float4*>(&pool[row * 64 + c4 * 4]) =
                in4[(size_t)(i0 + row) * 64 + kc * 16 + c4];
            *reinterpret_cast<float4*>(&pool[4096 + row * 64 + c4 * 4]) =
                W4[(size_t)(kc * 64 + row) * 16 + c4];
        }
        __syncthreads();
        #pragma unroll 8
        for (int kk = 0; kk < 64; ++kk) {
            const float4 wv = *reinterpret_cast<const float4*>(&pool[4096 + kk * 64 + f4]);
            #pragma unroll
            for (int r = 0; r < 2; ++r) {
                const float iv = pool[(i2 + r) * 64 + kk];
                c[r][0] = fmaf(iv, wv.x, c[r][0]);
                c[r][1] = fmaf(iv, wv.y, c[r][1]);
                c[r][2] = fmaf(iv, wv.z, c[r][2]);
                c[r][3] = fmaf(iv, wv.w, c[r][3]);
            }
        }
    }

    // stage fp32 h into padded smem h_s[64][65]
    __syncthreads();
    #pragma unroll
    for (int r = 0; r < 2; ++r) {
        float* row = &pool[(i2 + r) * 65 + f4];
        row[0] = c[r][0]; row[1] = c[r][1]; row[2] = c[r][2]; row[3] = c[r][3];
    }
    __syncthreads();

    // s1 / s2 (exact fp32), prescaled by log2(e); chip-wide max of s2'
    if (t < 64) {
        float s1 = 0.f, s2 = 0.f;
        #pragma unroll 8
        for (int f = 0; f < 64; ++f) {
            const float hv = pool[t * 65 + f];
            s1 = fmaf(hv, __ldg(&a[f]), s1);
            s2 = fmaf(hv, __ldg(&a[64 + f]), s2);
        }
        g_s1[i0 + t] = s1 * LOG2E;
        const float s2p = s2 * LOG2E;
        g_s2[i0 + t] = s2p;
        float m = s2p;
        #pragma unroll
        for (int d = 16; d; d >>= 1)
            m = fmaxf(m, __shfl_xor_sync(0xffffffffu, m, d));
        if ((t & 31) == 0) atomicMax(&g_s2key, fenc(m));
    }

    // pi-permuted fragment-packed fp16 h:
    // per 16-row block, entry (q,f): .x=(h[4q],h[4q+1]), .y=(h[4q+2],h[4q+3])
    #pragma unroll
    for (int e = 0; e < 2; ++e) {
        const int idx = t + e * 512;        // 0..1023
        const int blk = idx >> 8;           // 0..3
        const int q   = (idx >> 6) & 3;
        const int f   = idx & 63;
        const int rb  = blk * 16 + 4 * q;
        uint2 v;
        v.x = packh2(pool[(rb + 0) * 65 + f], pool[(rb + 1) * 65 + f]);
        v.y = packh2(pool[(rb + 2) * 65 + f], pool[(rb + 3) * 65 + f]);
        g_hp[((i0 >> 4) + blk) * 256 + q * 64 + f] = v;
    }
}

// ============================================================================
// Kernel 2: fused fp16 HMMA GEMM — A fragments built in registers from adj
// (pi-permuted: lane tig owns j 4tig..4tig+3, contiguous int4 loads),
// B staged from pre-packed g_hp (double-buffered). Grid (64, 16), 256 thr.
// ============================================================================
__global__ __launch_bounds__(256, 2) void k_mma(const int* __restrict__ adj)
{
    __shared__ float s2s[KCHUNK];                      // 2 KB
    __shared__ __align__(16) uint2 Bs[2][16][68];      // 17 KB

    const int t = threadIdx.x;
    const int w = t >> 5;
    const int l = t & 31;
    const int gid = l >> 2;
    const int tig = l & 3;
    const int i0 = blockIdx.x * TM;
    const int js = blockIdx.y;
    const int j0 = js * KCHUNK;
    const int r0 = w * 16 + gid;
    const int r1 = r0 + 8;

    // stage s2 chunk (512 values, 256 threads)
    #pragma unroll
    for (int e = 0; e < 2; ++e)
        s2s[t + e * 256] = g_s2[j0 + t + e * 256];

    // per-row constants (log2-domain, with overflow-bound m2 folded in)
    const float s2m = fdec(g_s2key);
    float s1a0, s1b0, mc0, s1a1, s1b1, mc1;
    {
        const float s1r = g_s1[i0 + r0];
        const float tt = s1r + s2m;
        const float m2 = fmaxf(fmaxf(tt, 0.2f * tt), NEG10L2E);
        s1a0 = s1r - m2;
        s1b0 = 0.2f * s1r - m2;
        mc0 = NEG10L2E - m2;
    }
    {
        const float s1r = g_s1[i0 + r1];
        const float tt = s1r + s2m;
        const float m2 = fmaxf(fmaxf(tt, 0.2f * tt), NEG10L2E);
        s1a1 = s1r - m2;
        s1b1 = 0.2f * s1r - m2;
        mc1 = NEG10L2E - m2;
    }

    const int4* a0p = reinterpret_cast<const int4*>(
        adj + (size_t)(i0 + r0) * N_NODES + j0) + tig;
    const int4* a1p = reinterpret_cast<const int4*>(
        adj + (size_t)(i0 + r1) * N_NODES + j0) + tig;

    float c[8][4];
    #pragma unroll
    for (int nt = 0; nt < 8; ++nt) {
        c[nt][0] = 0.f; c[nt][1] = 0.f; c[nt][2] = 0.f; c[nt][3] = 0.f;
    }
    float lac0 = 0.f, lac1 = 0.f;

    // stage B tile 0 into buffer 0
    {
        const uint4* src = reinterpret_cast<const uint4*>(g_hp) + ((size_t)j0 >> 4) * 128;
        const uint4 e0 = __ldg(&src[t]);
        const uint4 e1 = __ldg(&src[t + 256]);
        *reinterpret_cast<uint4*>(&Bs[0][t >> 5][(2 * t) & 63]) = e0;
        *reinterpret_cast<uint4*>(&Bs[0][(t >> 5) + 8][(2 * t) & 63]) = e1;
    }

    for (int tile = 0; tile < NT; ++tile) {
        const int buf = tile & 1;

        // adj loads for this tile: 8 LDG.128, contiguous 64B per row per quad
        int4 av0[4], av1[4];
        #pragma unroll
        for (int ks = 0; ks < 4; ++ks) {
            av0[ks] = __ldg(a0p + tile * 16 + ks * 4);
            av1[ks] = __ldg(a1p + tile * 16 + ks * 4);
        }

        __syncthreads();   // Bs[buf] staged; prior reads of Bs[buf^1] done

        // stage next tile into the other buffer
        if (tile + 1 < NT) {
            const uint4* src = reinterpret_cast<const uint4*>(g_hp) +
                               ((size_t)(j0 + (tile + 1) * TKJ) >> 4) * 128;
            const uint4 e0 = __ldg(&src[t]);
            const uint4 e1 = __ldg(&src[t + 256]);
            *reinterpret_cast<uint4*>(&Bs[buf ^ 1][t >> 5][(2 * t) & 63]) = e0;
            *reinterpret_cast<uint4*>(&Bs[buf ^ 1][(t >> 5) + 8][(2 * t) & 63]) = e1;
        }

        #pragma unroll
        for (int ks = 0; ks < 4; ++ks) {
            const float4 s4 = *reinterpret_cast<const float4*>(
                s2s + tile * TKJ + ks * 16 + 4 * tig);

            const float w00 = wgt(s1a0, s1b0, mc0, s4.x, av0[ks].x);
            const float w01 = wgt(s1a0, s1b0, mc0, s4.y, av0[ks].y);
            const float w02 = wgt(s1a0, s1b0, mc0, s4.z, av0[ks].z);
            const float w03 = wgt(s1a0, s1b0, mc0, s4.w, av0[ks].w);
            const float w10 = wgt(s1a1, s1b1, mc1, s4.x, av1[ks].x);
            const float w11 = wgt(s1a1, s1b1, mc1, s4.y, av1[ks].y);
            const float w12 = wgt(s1a1, s1b1, mc1, s4.z, av1[ks].z);
            const float w13 = wgt(s1a1, s1b1, mc1, s4.w, av1[ks].w);

            lac0 += (w00 + w01) + (w02 + w03);
            lac1 += (w10 + w11) + (w12 + w13);

            // pi-permuted fragment slots: a0=(j 4tig,4tig+1) r0, a2=(4tig+2,+3) r0
            const uint32_t A0 = packh2(w00, w01);
            const uint32_t A1 = packh2(w10, w11);
            const uint32_t A2 = packh2(w02, w03);
            const uint32_t A3 = packh2(w12, w13);

            const uint2* brow = &Bs[buf][ks * 4 + tig][gid];
            #pragma unroll
            for (int nt = 0; nt < 8; ++nt) {
                const uint2 b = brow[nt * 8];
                mma_fp16(c[nt], A0, A1, A2, A3, b.x, b.y);
            }
        }
    }

    // epilogue: D partials (scaled by 2^-m2 per row — cancels in k_reduce)
    #pragma unroll
    for (int nt = 0; nt < 8; ++nt) {
        const int col = nt * 8 + tig * 2;
        *reinterpret_cast<float2*>(&g_part[js][i0 + r0][col]) =
            make_float2(c[nt][0], c[nt][1]);
        *reinterpret_cast<float2*>(&g_part[js][i0 + r1][col]) =
            make_float2(c[nt][2], c[nt][3]);
    }

    // l partials: reduce across the 4 tig-lanes sharing each row
    lac0 += __shfl_xor_sync(0xffffffffu, lac0, 1);
    lac0 += __shfl_xor_sync(0xffffffffu, lac0, 2);
    lac1 += __shfl_xor_sync(0xffffffffu, lac1, 1);
    lac1 += __shfl_xor_sync(0xffffffffu, lac1, 2);
    if (tig == 0) {
        g_lpart[js][i0 + r0] = lac0;
        g_lpart[js][i0 + r1] = lac1;
    }
}

// ============================================================================
// Kernel 3: reduce 16 partials, normalize, ELU. float4 per thread.
// ============================================================================
__global__ __launch_bounds__(256) void k_reduce(float* __restrict__ out)
{
    const int gi = blockIdx.x * 256 + threadIdx.x;   // over N*16
    const int i = gi >> 4;
    const int f4 = (gi & 15) * 4;

    float4 s = make_float4(0.f, 0.f, 0.f, 0.f);
    float lsum = 0.f;
    #pragma unroll
    for (int p = 0; p < JSPLIT; ++p) {
        const float4 v = *reinterpret_cast<const float4*>(&g_part[p][i][f4]);
        s.x += v.x; s.y += v.y; s.z += v.z; s.w += v.w;
        lsum += g_lpart[p][i];
    }
    const float inv = 1.0f / lsum;
    float4 o;
    o.x = s.x * inv; o.y = s.y * inv; o.z = s.z * inv; o.w = s.w * inv;
    o.x = o.x > 0.f ? o.x : (__expf(o.x) - 1.f);
    o.y = o.y > 0.f ? o.y : (__expf(o.y) - 1.f);
    o.z = o.z > 0.f ? o.z : (__expf(o.z) - 1.f);
    o.w = o.w > 0.f ? o.w : (__expf(o.w) - 1.f);
    *reinterpret_cast<float4*>(&out[(size_t)i * FOUT + f4]) = o;
}

// ============================================================================
extern "C" void kernel_launch(void* const* d_in, const int* in_sizes, int n_in,
                              void* d_out, int out_size)
{
    const float* input = (const float*)d_in[0];  // [8192, 256]
    const int*   adj   = (const int*)  d_in[1];  // [8192, 8192]
    const float* W     = (const float*)d_in[2];  // [256, 64]
    const float* a     = (const float*)d_in[3];  // [128, 1]
    float* out = (float*)d_out;                  // [8192, 64]

    k_h<<<N_NODES / 64, 512>>>(input, W, a);
    k_mma<<<dim3(N_NODES / TM, JSPLIT), 256>>>(adj);
    k_reduce<<<(N_NODES * 16) / 256, 256>>>(out);
}

// round 12
// speedup vs baseline: 2.0732x; 1.0884x over previous
#include <cuda_runtime.h>
#include <cstdint>

#define N_NODES 8192
#define FIN 256
#define FOUT 64
#define LOG2E 1.4426950408889634f
#define NEG10L2E (-14.426950408889634f)

// ---- k_mma geometry ----
#define TM 128
#define TKJ 64
#define JSPLIT 16
#define KCHUNK (N_NODES / JSPLIT)    // 512
#define NT (KCHUNK / TKJ)            // 8

// dynamic smem layout for k_mma
#define BS_BYTES (8 * 16 * 68 * 8)   // 69632
#define SMEM_MMA (BS_BYTES + KCHUNK * 4)   // +2048 = 71680

// ---- scratch (allocation-free rule) ----
__device__ float g_s1[N_NODES];                    // prescaled by LOG2E
__device__ float g_s2[N_NODES];                    // prescaled by LOG2E
__device__ uint2 g_hp[(N_NODES / 16) * 256];       // fragment-packed fp16 h, 1 MB
__device__ float g_part[JSPLIT][N_NODES][FOUT];    // 32 MB
__device__ float g_lpart[JSPLIT][N_NODES];         // 512 KB
__device__ unsigned g_s2key = 0u;                  // ordered-key max of s2' (idempotent)

__device__ __forceinline__ unsigned fenc(float f) {
    unsigned u = __float_as_uint(f);
    return u ^ ((unsigned)((int)u >> 31) | 0x80000000u);
}
__device__ __forceinline__ float fdec(unsigned u) {
    unsigned b = (u & 0x80000000u) ? (u ^ 0x80000000u) : ~u;
    return __uint_as_float(b);
}
__device__ __forceinline__ float ex2(float x) {
    float r;
    asm("ex2.approx.f32 %0, %1;" : "=f"(r) : "f"(x));
    return r;
}
__device__ __forceinline__ uint32_t packh2(float lo, float hi) {
    uint32_t r;
    asm("cvt.rn.f16x2.f32 %0, %1, %2;" : "=r"(r) : "f"(hi), "f"(lo));
    return r;
}
__device__ __forceinline__ void mma_fp16(float c[4],
    uint32_t a0, uint32_t a1, uint32_t a2, uint32_t a3,
    uint32_t b0, uint32_t b1)
{
    asm volatile(
        "mma.sync.aligned.m16n8k16.row.col.f32.f16.f16.f32 "
        "{%0,%1,%2,%3}, {%4,%5,%6,%7}, {%8,%9}, {%0,%1,%2,%3};"
        : "+f"(c[0]), "+f"(c[1]), "+f"(c[2]), "+f"(c[3])
        : "r"(a0), "r"(a1), "r"(a2), "r"(a3), "r"(b0), "r"(b1));
}
// weight in log2 domain: lrelu2 - m2 folded into per-row consts
__device__ __forceinline__ float wgt(float s1a, float s1b, float mc,
                                     float s2, int av) {
    const float t1 = s1a + s2;
    const float t2 = fmaf(0.2f, s2, s1b);
    float y = fmaxf(t1, t2);
    y = (av > 0) ? y : mc;
    return ex2(y);
}

// ============================================================================
// Kernel 1: h = input @ W (64-row tiles, register-prefetched chunks); emit
// prescaled s1,s2, s2'-max, pi-permuted fp16 B. Grid: 128 blocks, 512 thr.
// ============================================================================
__global__ __launch_bounds__(512) void k_h(
    const float* __restrict__ input,   // [N, FIN]
    const float* __restrict__ W,       // [FIN, FOUT]
    const float* __restrict__ a)       // [2*FOUT]
{
    __shared__ float pool[8192];       // in_s[64][64] @0 | w_s[64][64] @4096
    const int t = threadIdx.x;         // 0..511
    const int i0 = blockIdx.x * 64;
    const int f4 = (t & 15) * 4;
    const int i2 = (t >> 4) * 2;       // 2 rows per thread

    const float4* in4 = reinterpret_cast<const float4*>(input);
    const float4* W4  = reinterpret_cast<const float4*>(W);

    // prefetch regs for one chunk: 2 input float4 + 2 W float4 per thread
    float4 pin[2], pw[2];
    const int ldrow0 = t >> 4, ldc0 = t & 15;
    const int ldrow1 = (t + 512) >> 4, ldc1 = (t + 512) & 15;

    pin[0] = in4[(size_t)(i0 + ldrow0) * 64 + ldc0];
    pin[1] = in4[(size_t)(i0 + ldrow1) * 64 + ldc1];
    pw[0]  = W4[(size_t)ldrow0 * 16 + ldc0];
    pw[1]  = W4[(size_t)ldrow1 * 16 + ldc1];

    float c[2][4];
    #pragma unroll
    for (int r = 0; r < 2; ++r) { c[r][0]=0.f; c[r][1]=0.f; c[r][2]=0.f; c[r][3]=0.f; }

    for (int kc = 0; kc < 4; ++kc) {
        __syncthreads();   // prev FMA done reading pool (no-op first iter)
        *reinterpret_cast<float4*>(&pool[ldrow0 * 64 + ldc0 * 4]) = pin[0];
        *reinterpret_cast<float4*>(&pool[ldrow1 * 64 + ldc1 * 4]) = pin[1];
        *reinterpret_cast<float4*>(&pool[4096 + ldrow0 * 64 + ldc0 * 4]) = pw[0];
        *reinterpret_cast<float4*>(&pool[4096 + ldrow1 * 64 + ldc1 * 4]) = pw[1];
        __syncthreads();

        if (kc < 3) {      // prefetch next chunk; latency hidden by FMA loop
            pin[0] = in4[(size_t)(i0 + ldrow0) * 64 + (kc + 1) * 16 + ldc0];
            pin[1] = in4[(size_t)(i0 + ldrow1) * 64 + (kc + 1) * 16 + ldc1];
            pw[0]  = W4[(size_t)((kc + 1) * 64 + ldrow0) * 16 + ldc0];
            pw[1]  = W4[(size_t)((kc + 1) * 64 + ldrow1) * 16 + ldc1];
        }

        #pragma unroll 8
        for (int kk = 0; kk < 64; ++kk) {
            const float4 wv = *reinterpret_cast<const float4*>(&pool[4096 + kk * 64 + f4]);
            #pragma unroll
            for (int r = 0; r < 2; ++r) {
                const float iv = pool[(i2 + r) * 64 + kk];
                c[r][0] = fmaf(iv, wv.x, c[r][0]);
                c[r][1] = fmaf(iv, wv.y, c[r][1]);
                c[r][2] = fmaf(iv, wv.z, c[r][2]);
                c[r][3] = fmaf(iv, wv.w, c[r][3]);
            }
        }
    }

    // stage fp32 h into padded smem h_s[64][65]
    __syncthreads();
    #pragma unroll
    for (int r = 0; r < 2; ++r) {
        float* row = &pool[(i2 + r) * 65 + f4];
        row[0] = c[r][0]; row[1] = c[r][1]; row[2] = c[r][2]; row[3] = c[r][3];
    }
    __syncthreads();

    // s1 / s2 (exact fp32), prescaled by log2(e); chip-wide max of s2'
    if (t < 64) {
        float s1 = 0.f, s2 = 0.f;
        #pragma unroll 8
        for (int f = 0; f < 64; ++f) {
            const float hv = pool[t * 65 + f];
            s1 = fmaf(hv, __ldg(&a[f]), s1);
            s2 = fmaf(hv, __ldg(&a[64 + f]), s2);
        }
        g_s1[i0 + t] = s1 * LOG2E;
        const float s2p = s2 * LOG2E;
        g_s2[i0 + t] = s2p;
        float m = s2p;
        #pragma unroll
        for (int d = 16; d; d >>= 1)
            m = fmaxf(m, __shfl_xor_sync(0xffffffffu, m, d));
        if ((t & 31) == 0) atomicMax(&g_s2key, fenc(m));
    }

    // pi-permuted fragment-packed fp16 h:
    // per 16-row block, entry (q,f): .x=(h[4q],h[4q+1]), .y=(h[4q+2],h[4q+3])
    #pragma unroll
    for (int e = 0; e < 2; ++e) {
        const int idx = t + e * 512;        // 0..1023
        const int blk = idx >> 8;           // 0..3
        const int q   = (idx >> 6) & 3;
        const int f   = idx & 63;
        const int rb  = blk * 16 + 4 * q;
        uint2 v;
        v.x = packh2(pool[(rb + 0) * 65 + f], pool[(rb + 1) * 65 + f]);
        v.y = packh2(pool[(rb + 2) * 65 + f], pool[(rb + 3) * 65 + f]);
        g_hp[((i0 >> 4) + blk) * 256 + q * 64 + f] = v;
    }
}

// ============================================================================
// Kernel 2: fused fp16 HMMA GEMM — whole B chunk (8 tiles, 64 KB) staged
// once, then a BARRIER-FREE main loop: warps free-run over 8 tiles, adj
// LDG.128s stream without barrier throttling. Grid (64, 16), 256 thr, occ 2.
// ============================================================================
__global__ __launch_bounds__(256, 2) void k_mma(const int* __restrict__ adj)
{
    extern __shared__ __align__(16) char smem[];
    uint2 (*Bs)[16][68] = reinterpret_cast<uint2 (*)[16][68]>(smem);   // [8][16][68]
    float* s2s = reinterpret_cast<float*>(smem + BS_BYTES);            // [512]

    const int t = threadIdx.x;
    const int w = t >> 5;
    const int l = t & 31;
    const int gid = l >> 2;
    const int tig = l & 3;
    const int i0 = blockIdx.x * TM;
    const int js = blockIdx.y;
    const int j0 = js * KCHUNK;
    const int r0 = w * 16 + gid;
    const int r1 = r0 + 8;

    // stage s2 chunk (512 values, 256 threads)
    #pragma unroll
    for (int e = 0; e < 2; ++e)
        s2s[t + e * 256] = g_s2[j0 + t + e * 256];

    // stage ALL 8 B tiles (64 KB contiguous from g_hp, L2-resident)
    {
        const uint4* src = reinterpret_cast<const uint4*>(g_hp) + ((size_t)j0 >> 4) * 128;
        #pragma unroll
        for (int k = 0; k < 16; ++k) {
            const int sg = t + k * 256;          // 0..4095
            const uint4 v = __ldg(src + sg);
            const int tile = sg >> 9;
            const int s    = sg & 511;
            *reinterpret_cast<uint4*>(&Bs[tile][s >> 5][(2 * s) & 63]) = v;
        }
    }

    // per-row constants (log2-domain, with overflow-bound m2 folded in)
    const float s2m = fdec(g_s2key);
    float s1a0, s1b0, mc0, s1a1, s1b1, mc1;
    {
        const float s1r = g_s1[i0 + r0];
        const float tt = s1r + s2m;
        const float m2 = fmaxf(fmaxf(tt, 0.2f * tt), NEG10L2E);
        s1a0 = s1r - m2;
        s1b0 = 0.2f * s1r - m2;
        mc0 = NEG10L2E - m2;
    }
    {
        const float s1r = g_s1[i0 + r1];
        const float tt = s1r + s2m;
        const float m2 = fmaxf(fmaxf(tt, 0.2f * tt), NEG10L2E);
        s1a1 = s1r - m2;
        s1b1 = 0.2f * s1r - m2;
        mc1 = NEG10L2E - m2;
    }

    const int4* a0p = reinterpret_cast<const int4*>(
        adj + (size_t)(i0 + r0) * N_NODES + j0) + tig;
    const int4* a1p = reinterpret_cast<const int4*>(
        adj + (size_t)(i0 + r1) * N_NODES + j0) + tig;

    float c[8][4];
    #pragma unroll
    for (int nt = 0; nt < 8; ++nt) {
        c[nt][0] = 0.f; c[nt][1] = 0.f; c[nt][2] = 0.f; c[nt][3] = 0.f;
    }
    float lac0 = 0.f, lac1 = 0.f;

    __syncthreads();   // the ONLY barrier: B + s2 staged

    #pragma unroll 1
    for (int tile = 0; tile < NT; ++tile) {
        // adj loads: 8 LDG.128, contiguous 64B per row per quad
        int4 av0[4], av1[4];
        #pragma unroll
        for (int ks = 0; ks < 4; ++ks) {
            av0[ks] = __ldg(a0p + tile * 16 + ks * 4);
            av1[ks] = __ldg(a1p + tile * 16 + ks * 4);
        }

        #pragma unroll
        for (int ks = 0; ks < 4; ++ks) {
            const float4 s4 = *reinterpret_cast<const float4*>(
                s2s + tile * TKJ + ks * 16 + 4 * tig);

            const float w00 = wgt(s1a0, s1b0, mc0, s4.x, av0[ks].x);
            const float w01 = wgt(s1a0, s1b0, mc0, s4.y, av0[ks].y);
            const float w02 = wgt(s1a0, s1b0, mc0, s4.z, av0[ks].z);
            const float w03 = wgt(s1a0, s1b0, mc0, s4.w, av0[ks].w);
            const float w10 = wgt(s1a1, s1b1, mc1, s4.x, av1[ks].x);
            const float w11 = wgt(s1a1, s1b1, mc1, s4.y, av1[ks].y);
            const float w12 = wgt(s1a1, s1b1, mc1, s4.z, av1[ks].z);
            const float w13 = wgt(s1a1, s1b1, mc1, s4.w, av1[ks].w);

            lac0 += (w00 + w01) + (w02 + w03);
            lac1 += (w10 + w11) + (w12 + w13);

            const uint32_t A0 = packh2(w00, w01);
            const uint32_t A1 = packh2(w10, w11);
            const uint32_t A2 = packh2(w02, w03);
            const uint32_t A3 = packh2(w12, w13);

            const uint2* brow = &Bs[tile][ks * 4 + tig][gid];
            #pragma unroll
            for (int nt = 0; nt < 8; ++nt) {
                const uint2 b = brow[nt * 8];
                mma_fp16(c[nt], A0, A1, A2, A3, b.x, b.y);
            }
        }
    }

    // epilogue: D partials (scaled by 2^-m2 per row — cancels in k_reduce)
    #pragma unroll
    for (int nt = 0; nt < 8; ++nt) {
        const int col = nt * 8 + tig * 2;
        *reinterpret_cast<float2*>(&g_part[js][i0 + r0][col]) =
            make_float2(c[nt][0], c[nt][1]);
        *reinterpret_cast<float2*>(&g_part[js][i0 + r1][col]) =
            make_float2(c[nt][2], c[nt][3]);
    }

    // l partials: reduce across the 4 tig-lanes sharing each row
    lac0 += __shfl_xor_sync(0xffffffffu, lac0, 1);
    lac0 += __shfl_xor_sync(0xffffffffu, lac0, 2);
    lac1 += __shfl_xor_sync(0xffffffffu, lac1, 1);
    lac1 += __shfl_xor_sync(0xffffffffu, lac1, 2);
    if (tig == 0) {
        g_lpart[js][i0 + r0] = lac0;
        g_lpart[js][i0 + r1] = lac1;
    }
}

// ============================================================================
// Kernel 3: reduce 16 partials, normalize, ELU. float4 per thread.
// ============================================================================
__global__ __launch_bounds__(256) void k_reduce(float* __restrict__ out)
{
    const int gi = blockIdx.x * 256 + threadIdx.x;   // over N*16
    const int i = gi >> 4;
    const int f4 = (gi & 15) * 4;

    float4 s = make_float4(0.f, 0.f, 0.f, 0.f);
    float lsum = 0.f;
    #pragma unroll
    for (int p = 0; p < JSPLIT; ++p) {
        const float4 v = *reinterpret_cast<const float4*>(&g_part[p][i][f4]);
        s.x += v.x; s.y += v.y; s.z += v.z; s.w += v.w;
        lsum += g_lpart[p][i];
    }
    const float inv = 1.0f / lsum;
    float4 o;
    o.x = s.x * inv; o.y = s.y * inv; o.z = s.z * inv; o.w = s.w * inv;
    o.x = o.x > 0.f ? o.x : (__expf(o.x) - 1.f);
    o.y = o.y > 0.f ? o.y : (__expf(o.y) - 1.f);
    o.z = o.z > 0.f ? o.z : (__expf(o.z) - 1.f);
    o.w = o.w > 0.f ? o.w : (__expf(o.w) - 1.f);
    *reinterpret_cast<float4*>(&out[(size_t)i * FOUT + f4]) = o;
}

// ============================================================================
extern "C" void kernel_launch(void* const* d_in, const int* in_sizes, int n_in,
                              void* d_out, int out_size)
{
    const float* input = (const float*)d_in[0];  // [8192, 256]
    const int*   adj   = (const int*)  d_in[1];  // [8192, 8192]
    const float* W     = (const float*)d_in[2];  // [256, 64]
    const float* a     = (const float*)d_in[3];  // [128, 1]
    float* out = (float*)d_out;                  // [8192, 64]

    cudaFuncSetAttribute(k_mma, cudaFuncAttributeMaxDynamicSharedMemorySize, SMEM_MMA);

    k_h<<<N_NODES / 64, 512>>>(input, W, a);
    k_mma<<<dim3(N_NODES / TM, JSPLIT), 256, SMEM_MMA>>>(adj);
    k_reduce<<<(N_NODES * 16) / 256, 256>>>(out);
}